// round 12
// baseline (speedup 1.0000x reference)
#include <cuda_runtime.h>
#include <cuda_fp16.h>
#include <cstdint>
#include <math.h>

// ----------------------------------------------------------------------------
// Problem constants
// ----------------------------------------------------------------------------
#define S_LEN   2048
#define DMODEL  2048
#define HQ      32
#define HKV     8
#define HD      64
#define KV_DIM  (HKV*HD)   // 512

// ----------------------------------------------------------------------------
// Scratch (static __device__ arrays: allocation-free)
// ----------------------------------------------------------------------------
__device__ __half g_hh[S_LEN * DMODEL],  g_hl[S_LEN * DMODEL];   // rmsnorm out (hi/lo)
__device__ __half g_wqt[DMODEL * DMODEL];                        // wq^T single fp16 [N,K]
__device__ __half g_kvt[2 * KV_DIM * DMODEL];                    // [wk^T; wv^T]
__device__ __half g_wot[DMODEL * DMODEL];
__device__ float  g_pq[S_LEN * DMODEL];
__device__ float  g_pkv[S_LEN * 2 * KV_DIM];
__device__ __half g_qh[S_LEN * DMODEL],  g_ql[S_LEN * DMODEL];   // roped+scaled q (hi/lo)
__device__ __half g_kh[S_LEN * KV_DIM];                          // roped k (single)
__device__ __half g_vh[S_LEN * KV_DIM];                          // v (single)
__device__ __half g_oh[S_LEN * DMODEL],  g_ol[S_LEN * DMODEL];   // attn out (hi/lo)

// ----------------------------------------------------------------------------
// PTX helpers
// ----------------------------------------------------------------------------
__device__ __forceinline__ void mma16816(float* c, const uint32_t* a,
                                         uint32_t b0, uint32_t b1) {
    asm volatile(
        "mma.sync.aligned.m16n8k16.row.col.f32.f16.f16.f32 "
        "{%0,%1,%2,%3}, {%4,%5,%6,%7}, {%8,%9}, {%0,%1,%2,%3};"
        : "+f"(c[0]), "+f"(c[1]), "+f"(c[2]), "+f"(c[3])
        : "r"(a[0]), "r"(a[1]), "r"(a[2]), "r"(a[3]), "r"(b0), "r"(b1));
}
__device__ __forceinline__ void ldsm4(uint32_t* r, uint32_t addr) {
    asm volatile("ldmatrix.sync.aligned.m8n8.x4.shared.b16 {%0,%1,%2,%3}, [%4];"
                 : "=r"(r[0]), "=r"(r[1]), "=r"(r[2]), "=r"(r[3]) : "r"(addr));
}
__device__ __forceinline__ void ldsm4t(uint32_t* r, uint32_t addr) {
    asm volatile("ldmatrix.sync.aligned.m8n8.x4.trans.shared.b16 {%0,%1,%2,%3}, [%4];"
                 : "=r"(r[0]), "=r"(r[1]), "=r"(r[2]), "=r"(r[3]) : "r"(addr));
}
__device__ __forceinline__ void cp16(uint32_t saddr, const void* g) {
    asm volatile("cp.async.cg.shared.global [%0], [%1], 16;" :: "r"(saddr), "l"(g));
}
__device__ __forceinline__ void cp_commit() {
    asm volatile("cp.async.commit_group;" ::: "memory");
}
__device__ __forceinline__ uint32_t scvta(const void* p) {
    return (uint32_t)__cvta_generic_to_shared(p);
}
__device__ __forceinline__ uint32_t pack_h2(float a, float b) {
    __half2 t = __floats2half2_rn(a, b);
    return *(uint32_t*)&t;
}

// ----------------------------------------------------------------------------
// RMSNorm: one block per row; writes fp16 hi/lo split
// ----------------------------------------------------------------------------
__global__ void rmsnorm_kernel(const float* __restrict__ x,
                               const float* __restrict__ g,
                               __half* __restrict__ hh, __half* __restrict__ hl) {
    const int s = blockIdx.x;
    const float2* xr = (const float2*)(x + (size_t)s * DMODEL);
    const float2* gr = (const float2*)g;
    float sum = 0.f;
    for (int d = threadIdx.x; d < DMODEL / 2; d += 256) {
        float2 v = xr[d];
        sum += v.x * v.x + v.y * v.y;
    }
    __shared__ float red[8];
    #pragma unroll
    for (int o = 16; o > 0; o >>= 1) sum += __shfl_xor_sync(0xffffffffu, sum, o);
    if ((threadIdx.x & 31) == 0) red[threadIdx.x >> 5] = sum;
    __syncthreads();
    if (threadIdx.x < 32) {
        float v = (threadIdx.x < 8) ? red[threadIdx.x] : 0.f;
        #pragma unroll
        for (int o = 4; o > 0; o >>= 1) v += __shfl_xor_sync(0xffffffffu, v, o);
        if (threadIdx.x == 0) red[0] = v;
    }
    __syncthreads();
    const float rinv = rsqrtf(red[0] / (float)DMODEL + 1e-9f);
    uint32_t* ph = (uint32_t*)(hh + (size_t)s * DMODEL);
    uint32_t* pl = (uint32_t*)(hl + (size_t)s * DMODEL);
    for (int d = threadIdx.x; d < DMODEL / 2; d += 256) {
        const float2 v = xr[d];
        const float2 gg = gr[d];
        const float a = v.x * rinv * gg.x, b = v.y * rinv * gg.y;
        const __half ha = __float2half_rn(a), hb = __float2half_rn(b);
        __half2 t = __halves2half2(ha, hb);
        ph[d] = *(uint32_t*)&t;
        pl[d] = pack_h2(a - __half2float(ha), b - __half2float(hb));
    }
}

// ----------------------------------------------------------------------------
// Transpose to single fp16: W[K,N] fp32 -> Wt [N,K] fp16
// ----------------------------------------------------------------------------
__global__ void transpose_half_kernel(const float* __restrict__ w,
                                      __half* __restrict__ t_out,
                                      int K, int N) {
    __shared__ float t[32][33];
    const int n0 = blockIdx.x * 32, k0 = blockIdx.y * 32;
    const int tx = threadIdx.x, ty = threadIdx.y;  // (32, 8)
    #pragma unroll
    for (int i = 0; i < 32; i += 8)
        t[ty + i][tx] = w[(size_t)(k0 + ty + i) * N + n0 + tx];
    __syncthreads();
    const int lt = ty * 32 + tx;
    const int n  = lt >> 3;
    const int kp = lt & 7;
    #pragma unroll
    for (int q = 0; q < 2; q++) {
        const int k2 = (kp + q * 8) * 2;
        const size_t o = (size_t)(n0 + n) * K + k0 + k2;
        *(uint32_t*)(t_out + o) = pack_h2(t[k2][n], t[k2 + 1][n]);
    }
}

// ----------------------------------------------------------------------------
// fp16x2 GEMM: C[M,N] = (Ah+Al) @ B^T (+Res), fp32 acc.
// A hi/lo [M,K] fp16, B single [N,K] fp16.
// Block 128x128, BK=32, 256 thr = 8 warps (2Mx4N), 3-stage cp.async,
// 2 CTAs/SM (92KB smem, <=128 regs).
// ----------------------------------------------------------------------------
#define KP 40
#define NSTAGE 3
#define T_STG (128 * KP * 2)                 // 10240 bytes per array per stage
#define GEMM_SMEM (NSTAGE * 3 * T_STG)       // 92160

__global__ __launch_bounds__(256, 2) void mma_gemm_kernel(
    const __half* __restrict__ Ah, const __half* __restrict__ Al,
    const __half* __restrict__ B,
    const float* __restrict__ Res, float* __restrict__ C,
    int N, int K) {
    extern __shared__ __align__(16) char sm[];
    const uint32_t smb = scvta(sm);
    const uint32_t oAH = 0;
    const uint32_t oAL = NSTAGE * T_STG;
    const uint32_t oB  = 2 * NSTAGE * T_STG;

    const int tid  = threadIdx.x;
    const int lane = tid & 31, wid = tid >> 5;
    const int bm = blockIdx.y * 128, bn = blockIdx.x * 128;
    const int wmb = (wid & 1) * 64;
    const int wnb = (wid >> 1) * 32;
    const int lr = lane >> 2, lc = (lane & 3) * 2;

    float acc[4][4][4];
    #pragma unroll
    for (int mt = 0; mt < 4; mt++)
        #pragma unroll
        for (int nt = 0; nt < 4; nt++)
            #pragma unroll
            for (int i = 0; i < 4; i++) acc[mt][nt][i] = 0.f;

    auto load_stage = [&](int s, int kc) {
        #pragma unroll
        for (int p = 0; p < 2; p++) {           // 512 chunks per array
            const int idx = tid + p * 256;
            const int r = idx >> 2, c8 = (idx & 3) * 8;
            const uint32_t off = (uint32_t)(r * KP + c8) * 2;
            const size_t ga = (size_t)(bm + r) * K + kc + c8;
            const size_t gb = (size_t)(bn + r) * K + kc + c8;
            cp16(smb + oAH + s * T_STG + off, Ah + ga);
            cp16(smb + oAL + s * T_STG + off, Al + ga);
            cp16(smb + oB  + s * T_STG + off, B  + gb);
        }
    };

    const int nch = K >> 5;
    load_stage(0, 0);
    cp_commit();
    load_stage(1, 32);
    cp_commit();

    const int a_row = lane & 15;
    const int a_kof = (lane >> 4) << 3;
    const int b_row = (lane & 7) + ((lane >> 4) << 3);
    const int b_kof = ((lane >> 3) & 1) << 3;

    for (int c = 0; c < nch; c++) {
        if (c + 1 < nch) asm volatile("cp.async.wait_group 1;" ::: "memory");
        else             asm volatile("cp.async.wait_group 0;" ::: "memory");
        __syncthreads();
        if (c + 2 < nch) {
            load_stage((c + 2) % NSTAGE, (c + 2) * 32);
            cp_commit();
        }
        const int cur = c % NSTAGE;
        const uint32_t sAh = smb + oAH + cur * T_STG;
        const uint32_t sAl = smb + oAL + cur * T_STG;
        const uint32_t sB  = smb + oB  + cur * T_STG;

        #pragma unroll
        for (int kk = 0; kk < 32; kk += 16) {
            uint32_t fah[4][4], fal[4][4];
            #pragma unroll
            for (int mt = 0; mt < 4; mt++) {
                const uint32_t off = (uint32_t)((wmb + mt * 16 + a_row) * KP + kk + a_kof) * 2;
                ldsm4(fah[mt], sAh + off);
                ldsm4(fal[mt], sAl + off);
            }
            #pragma unroll
            for (int p2 = 0; p2 < 2; p2++) {
                const uint32_t off = (uint32_t)((wnb + p2 * 16 + b_row) * KP + kk + b_kof) * 2;
                uint32_t rb[4];
                ldsm4(rb, sB + off);
                #pragma unroll
                for (int mt = 0; mt < 4; mt++) {
                    mma16816(acc[mt][2 * p2],     fah[mt], rb[0], rb[1]);
                    mma16816(acc[mt][2 * p2],     fal[mt], rb[0], rb[1]);
                    mma16816(acc[mt][2 * p2 + 1], fah[mt], rb[2], rb[3]);
                    mma16816(acc[mt][2 * p2 + 1], fal[mt], rb[2], rb[3]);
                }
            }
        }
        __syncthreads();
    }

    #pragma unroll
    for (int mt = 0; mt < 4; mt++) {
        const int row0 = bm + wmb + mt * 16 + lr;
        #pragma unroll
        for (int nt = 0; nt < 4; nt++) {
            const int col = bn + wnb + nt * 8 + lc;
            float2 v0 = make_float2(acc[mt][nt][0], acc[mt][nt][1]);
            float2 v1 = make_float2(acc[mt][nt][2], acc[mt][nt][3]);
            if (Res) {
                const float2 q0 = *(const float2*)(Res + (size_t)row0 * N + col);
                const float2 q1 = *(const float2*)(Res + (size_t)(row0 + 8) * N + col);
                v0.x += q0.x; v0.y += q0.y;
                v1.x += q1.x; v1.y += q1.y;
            }
            *(float2*)(C + (size_t)row0 * N + col) = v0;
            *(float2*)(C + (size_t)(row0 + 8) * N + col) = v1;
        }
    }
}

// ----------------------------------------------------------------------------
// RoPE + scale + fp16 split (lo optional: pass ol=nullptr for single output)
// ----------------------------------------------------------------------------
__global__ void rope_split_kernel(const float* __restrict__ src, int src_stride,
                                  __half* __restrict__ oh, __half* __restrict__ ol,
                                  int o_stride, int H, float scale, int total) {
    int idx = blockIdx.x * blockDim.x + threadIdx.x;
    if (idx >= total) return;
    const int i2 = idx & 15;
    const int h = (idx >> 4) % H;
    const int s = idx / (16 * H);
    const float* p = src + (size_t)s * src_stride + h * HD;
    float y[4];
    #pragma unroll
    for (int q = 0; q < 2; q++) {
        const int i = 2 * i2 + q;
        const double inv = pow(10000.0, -(double)(2 * i) / (double)HD);
        const double ang = (double)s * inv;
        const float cs = (float)cos(ang);
        const float sn = (float)sin(ang);
        const float x1 = p[i], x2 = p[i + 32];
        y[q]     = (x1 * cs - x2 * sn) * scale;
        y[2 + q] = (x1 * sn + x2 * cs) * scale;
    }
    __half* ph = oh + (size_t)s * o_stride + h * HD;
    const __half b0 = __float2half_rn(y[0]), b1 = __float2half_rn(y[1]);
    const __half b2 = __float2half_rn(y[2]), b3 = __float2half_rn(y[3]);
    __half2 t;
    t = __halves2half2(b0, b1); *(uint32_t*)(ph + 2 * i2) = *(uint32_t*)&t;
    t = __halves2half2(b2, b3); *(uint32_t*)(ph + 2 * i2 + 32) = *(uint32_t*)&t;
    if (ol) {
        __half* pl = ol + (size_t)s * o_stride + h * HD;
        *(uint32_t*)(pl + 2 * i2)      = pack_h2(y[0] - __half2float(b0),
                                                 y[1] - __half2float(b1));
        *(uint32_t*)(pl + 2 * i2 + 32) = pack_h2(y[2] - __half2float(b2),
                                                 y[3] - __half2float(b3));
    }
}

// ----------------------------------------------------------------------------
// Strided fp16 convert for V (single)
// ----------------------------------------------------------------------------
__global__ void split_v_kernel(const float* __restrict__ src,
                               __half* __restrict__ hi) {
    int i = blockIdx.x * blockDim.x + threadIdx.x;
    if (i >= S_LEN * KV_DIM / 2) return;
    const int s = i >> 8, c2 = (i & 255) * 2;
    const float2 v = *(const float2*)(src + (size_t)s * (2 * KV_DIM) + KV_DIM + c2);
    *(uint32_t*)(hi + (size_t)s * KV_DIM + c2) = pack_h2(v.x, v.y);
}

// ----------------------------------------------------------------------------
// Tensor-core causal GQA flash attention (fp16x2).
// Grid (S/128, HQ). 256 threads = 8 warps x 16 q-rows. KV tiles of 64.
// Q hi/lo, K single; P hi/lo, V single. Writes O hi/lo fp16.
// ----------------------------------------------------------------------------
#define AQP 72

__global__ __launch_bounds__(256) void attn_mma_kernel(
    const __half* __restrict__ qh, const __half* __restrict__ ql,
    const __half* __restrict__ kh, const __half* __restrict__ vh,
    __half* __restrict__ oh, __half* __restrict__ ol) {
    __shared__ __align__(16) char sbuf[36864];
    __half* QH = (__half*)sbuf;                 // [128][72]
    __half* QL = (__half*)(sbuf + 18432);
    __half* KH = (__half*)sbuf;                 // [64][72] (reuse after Q frags)
    __half* VH = (__half*)(sbuf + 9216);        // [64][72] natural layout

    const int qt = blockIdx.x, h = blockIdx.y;
    const int kvh = h >> 2;
    const int tid = threadIdx.x, lane = tid & 31, wid = tid >> 5;
    const int lr = lane >> 2, lc = (lane & 3) * 2;

    // ---- stage Q ----
    #pragma unroll
    for (int p = 0; p < 4; p++) {
        const int idx = tid + p * 256;
        const int r = idx >> 3, c8 = (idx & 7) * 8;
        const size_t go = (size_t)(qt * 128 + r) * DMODEL + h * HD + c8;
        *(uint4*)(QH + r * AQP + c8) = *(const uint4*)(qh + go);
        *(uint4*)(QL + r * AQP + c8) = *(const uint4*)(ql + go);
    }
    __syncthreads();

    uint32_t qfh[4][4], qfl[4][4];
    {
        const int a_row = lane & 15;
        const int a_kof = (lane >> 4) << 3;
        #pragma unroll
        for (int ks = 0; ks < 4; ks++) {
            const uint32_t off = (uint32_t)((wid * 16 + a_row) * AQP + ks * 16 + a_kof) * 2;
            ldsm4(qfh[ks], scvta(QH) + off);
            ldsm4(qfl[ks], scvta(QL) + off);
        }
    }
    __syncthreads();

    float o[8][4];
    #pragma unroll
    for (int n = 0; n < 8; n++)
        #pragma unroll
        for (int i = 0; i < 4; i++) o[n][i] = 0.f;
    float m0 = -1e30f, m1 = -1e30f, l0 = 0.f, l1 = 0.f;

    const int row0g = qt * 128 + wid * 16 + lr;
    const int row1g = row0g + 8;
    const int nkt = 2 * qt + 2;

    const int b_row = (lane & 7) + ((lane >> 4) << 3);
    const int b_kof = ((lane >> 3) & 1) << 3;
    const int v_row = lane & 15;
    const int v_col = (lane >> 4) << 3;

    for (int kt = 0; kt < nkt; kt++) {
        // ---- load K and V tiles [kv][d] (single fp16 each) ----
        #pragma unroll
        for (int p = 0; p < 2; p++) {
            const int idx = tid + p * 256;
            const int r = idx >> 3, c8 = (idx & 7) * 8;
            const size_t go = (size_t)(kt * 64 + r) * KV_DIM + kvh * HD + c8;
            *(uint4*)(KH + r * AQP + c8) = *(const uint4*)(kh + go);
            *(uint4*)(VH + r * AQP + c8) = *(const uint4*)(vh + go);
        }
        __syncthreads();

        // ---- S = Q K^T (2-product) ----
        float s[8][4];
        #pragma unroll
        for (int n = 0; n < 8; n++)
            #pragma unroll
            for (int i = 0; i < 4; i++) s[n][i] = 0.f;
        #pragma unroll
        for (int ks = 0; ks < 4; ks++) {
            #pragma unroll
            for (int p2 = 0; p2 < 4; p2++) {
                const uint32_t off = (uint32_t)((p2 * 16 + b_row) * AQP + ks * 16 + b_kof) * 2;
                uint32_t rk[4];
                ldsm4(rk, scvta(KH) + off);
                mma16816(s[2 * p2],     qfh[ks], rk[0], rk[1]);
                mma16816(s[2 * p2],     qfl[ks], rk[0], rk[1]);
                mma16816(s[2 * p2 + 1], qfh[ks], rk[2], rk[3]);
                mma16816(s[2 * p2 + 1], qfl[ks], rk[2], rk[3]);
            }
        }

        // ---- causal mask ----
        if (kt >= 2 * qt) {
            #pragma unroll
            for (int n = 0; n < 8; n++) {
                const int colb = kt * 64 + n * 8 + lc;
                if (colb     > row0g) s[n][0] = -1e30f;
                if (colb + 1 > row0g) s[n][1] = -1e30f;
                if (colb     > row1g) s[n][2] = -1e30f;
                if (colb + 1 > row1g) s[n][3] = -1e30f;
            }
        }

        // ---- online softmax ----
        float tm0 = -1e30f, tm1 = -1e30f;
        #pragma unroll
        for (int n = 0; n < 8; n++) {
            tm0 = fmaxf(tm0, fmaxf(s[n][0], s[n][1]));
            tm1 = fmaxf(tm1, fmaxf(s[n][2], s[n][3]));
        }
        tm0 = fmaxf(tm0, __shfl_xor_sync(0xffffffffu, tm0, 1));
        tm0 = fmaxf(tm0, __shfl_xor_sync(0xffffffffu, tm0, 2));
        tm1 = fmaxf(tm1, __shfl_xor_sync(0xffffffffu, tm1, 1));
        tm1 = fmaxf(tm1, __shfl_xor_sync(0xffffffffu, tm1, 2));
        const float mn0 = fmaxf(m0, tm0), mn1 = fmaxf(m1, tm1);
        const float a0 = __expf(m0 - mn0), a1 = __expf(m1 - mn1);
        m0 = mn0; m1 = mn1;

        uint32_t pA[8], pB[8], pAl[8], pBl[8];
        float rs0 = 0.f, rs1 = 0.f;
        #pragma unroll
        for (int n = 0; n < 8; n++) {
            const float p0 = __expf(s[n][0] - m0);
            const float p1 = __expf(s[n][1] - m0);
            const float p2 = __expf(s[n][2] - m1);
            const float p3 = __expf(s[n][3] - m1);
            rs0 += p0 + p1; rs1 += p2 + p3;
            const __half h0 = __float2half_rn(p0), h1 = __float2half_rn(p1);
            const __half h2 = __float2half_rn(p2), h3 = __float2half_rn(p3);
            __half2 t;
            t = __halves2half2(h0, h1); pA[n] = *(uint32_t*)&t;
            t = __halves2half2(h2, h3); pB[n] = *(uint32_t*)&t;
            pAl[n] = pack_h2(p0 - __half2float(h0), p1 - __half2float(h1));
            pBl[n] = pack_h2(p2 - __half2float(h2), p3 - __half2float(h3));
        }
        rs0 += __shfl_xor_sync(0xffffffffu, rs0, 1);
        rs0 += __shfl_xor_sync(0xffffffffu, rs0, 2);
        rs1 += __shfl_xor_sync(0xffffffffu, rs1, 1);
        rs1 += __shfl_xor_sync(0xffffffffu, rs1, 2);
        l0 = l0 * a0 + rs0;
        l1 = l1 * a1 + rs1;
        #pragma unroll
        for (int n = 0; n < 8; n++) {
            o[n][0] *= a0; o[n][1] *= a0;
            o[n][2] *= a1; o[n][3] *= a1;
        }

        // ---- O += P V  (P hi/lo, V single via ldmatrix.trans) ----
        #pragma unroll
        for (int j = 0; j < 4; j++) {
            uint32_t aH[4] = {pA[2*j], pB[2*j], pA[2*j+1], pB[2*j+1]};
            uint32_t aL[4] = {pAl[2*j], pBl[2*j], pAl[2*j+1], pBl[2*j+1]};
            #pragma unroll
            for (int p2 = 0; p2 < 4; p2++) {
                const uint32_t off =
                    (uint32_t)((j * 16 + v_row) * AQP + p2 * 16 + v_col) * 2;
                uint32_t rv[4];
                ldsm4t(rv, scvta(VH) + off);
                mma16816(o[2 * p2],     aH, rv[0], rv[1]);
                mma16816(o[2 * p2],     aL, rv[0], rv[1]);
                mma16816(o[2 * p2 + 1], aH, rv[2], rv[3]);
                mma16816(o[2 * p2 + 1], aL, rv[2], rv[3]);
            }
        }
        __syncthreads();
    }

    // ---- epilogue: normalize, split fp16 hi/lo ----
    const float i0 = 1.f / l0, i1 = 1.f / l1;
    #pragma unroll
    for (int n = 0; n < 8; n++) {
        const int col = h * HD + n * 8 + lc;
        {
            const float v0 = o[n][0] * i0, v1 = o[n][1] * i0;
            const __half b0 = __float2half_rn(v0), b1 = __float2half_rn(v1);
            __half2 t = __halves2half2(b0, b1);
            *(uint32_t*)(oh + (size_t)row0g * DMODEL + col) = *(uint32_t*)&t;
            *(uint32_t*)(ol + (size_t)row0g * DMODEL + col) =
                pack_h2(v0 - __half2float(b0), v1 - __half2float(b1));
        }
        {
            const float v0 = o[n][2] * i1, v1 = o[n][3] * i1;
            const __half b0 = __float2half_rn(v0), b1 = __float2half_rn(v1);
            __half2 t = __halves2half2(b0, b1);
            *(uint32_t*)(oh + (size_t)row1g * DMODEL + col) = *(uint32_t*)&t;
            *(uint32_t*)(ol + (size_t)row1g * DMODEL + col) =
                pack_h2(v0 - __half2float(b0), v1 - __half2float(b1));
        }
    }
}

// ----------------------------------------------------------------------------
// Launch
// ----------------------------------------------------------------------------
extern "C" void kernel_launch(void* const* d_in, const int* in_sizes, int n_in,
                              void* d_out, int out_size) {
    const float* x  = (const float*)d_in[0];
    const float* g  = (const float*)d_in[1];
    const float* wq = (const float*)d_in[2];
    const float* wk = (const float*)d_in[3];
    const float* wv = (const float*)d_in[4];
    const float* wo = (const float*)d_in[5];
    float* out = (float*)d_out;

    static bool inited = false;
    static __half *hh, *hl, *wqt, *kvt, *wot;
    static __half *qh, *ql, *kh, *vh, *oh, *ol;
    static float *pq, *pkv;
    if (!inited) {
        inited = true;
        cudaFuncSetAttribute(mma_gemm_kernel,
                             cudaFuncAttributeMaxDynamicSharedMemorySize, GEMM_SMEM);
        cudaGetSymbolAddress((void**)&hh,  g_hh);
        cudaGetSymbolAddress((void**)&hl,  g_hl);
        cudaGetSymbolAddress((void**)&wqt, g_wqt);
        cudaGetSymbolAddress((void**)&kvt, g_kvt);
        cudaGetSymbolAddress((void**)&wot, g_wot);
        cudaGetSymbolAddress((void**)&qh,  g_qh);
        cudaGetSymbolAddress((void**)&ql,  g_ql);
        cudaGetSymbolAddress((void**)&kh,  g_kh);
        cudaGetSymbolAddress((void**)&vh,  g_vh);
        cudaGetSymbolAddress((void**)&oh,  g_oh);
        cudaGetSymbolAddress((void**)&ol,  g_ol);
        cudaGetSymbolAddress((void**)&pq,  g_pq);
        cudaGetSymbolAddress((void**)&pkv, g_pkv);
    }

    // 1) RMSNorm -> fp16 hi/lo
    rmsnorm_kernel<<<S_LEN, 256>>>(x, g, hh, hl);

    // 2) Weight transposes (single fp16)
    dim3 tb(32, 8);
    transpose_half_kernel<<<dim3(DMODEL / 32, DMODEL / 32), tb>>>(wq, wqt, DMODEL, DMODEL);
    transpose_half_kernel<<<dim3(KV_DIM / 32, DMODEL / 32), tb>>>(wk, kvt, DMODEL, KV_DIM);
    transpose_half_kernel<<<dim3(KV_DIM / 32, DMODEL / 32), tb>>>(
        wv, kvt + (size_t)KV_DIM * DMODEL, DMODEL, KV_DIM);
    transpose_half_kernel<<<dim3(DMODEL / 32, DMODEL / 32), tb>>>(wo, wot, DMODEL, DMODEL);

    // 3) Projections (fp16x2 on HMMA)
    mma_gemm_kernel<<<dim3(DMODEL / 128, S_LEN / 128), 256, GEMM_SMEM>>>(
        hh, hl, wqt, nullptr, pq, DMODEL, DMODEL);
    mma_gemm_kernel<<<dim3(2 * KV_DIM / 128, S_LEN / 128), 256, GEMM_SMEM>>>(
        hh, hl, kvt, nullptr, pkv, 2 * KV_DIM, DMODEL);

    // 4) RoPE + converts (q scaled by 1/sqrt(HD), hi/lo; k,v single)
    {
        const int tq = S_LEN * HQ * 16;
        rope_split_kernel<<<(tq + 255) / 256, 256>>>(pq, DMODEL, qh, ql, DMODEL, HQ, 0.125f, tq);
        const int tk = S_LEN * HKV * 16;
        rope_split_kernel<<<(tk + 255) / 256, 256>>>(pkv, 2 * KV_DIM, kh, nullptr, KV_DIM, HKV, 1.0f, tk);
        split_v_kernel<<<(S_LEN * KV_DIM / 2 + 255) / 256, 256>>>(pkv, vh);
    }

    // 5) Attention
    attn_mma_kernel<<<dim3(S_LEN / 128, HQ), 256>>>(qh, ql, kh, vh, oh, ol);

    // 6) Output projection + residual
    mma_gemm_kernel<<<dim3(DMODEL / 128, S_LEN / 128), 256, GEMM_SMEM>>>(
        oh, ol, wot, x, out, DMODEL, DMODEL);
}

// round 14
// speedup vs baseline: 1.2224x; 1.2224x over previous
#include <cuda_runtime.h>
#include <cuda_fp16.h>
#include <cstdint>
#include <math.h>

// ----------------------------------------------------------------------------
// Problem constants
// ----------------------------------------------------------------------------
#define S_LEN   2048
#define DMODEL  2048
#define HQ      32
#define HKV     8
#define HD      64
#define KV_DIM  (HKV*HD)   // 512

// ----------------------------------------------------------------------------
// Scratch (static __device__ arrays: allocation-free)
// ----------------------------------------------------------------------------
__device__ __half g_h[S_LEN * DMODEL];           // rmsnorm out fp16
__device__ __half g_wqt[DMODEL * DMODEL];        // wq^T [N,K] fp16
__device__ __half g_kvt[2 * KV_DIM * DMODEL];    // [wk^T; wv^T]
__device__ __half g_wot[DMODEL * DMODEL];
__device__ float  g_pq[S_LEN * DMODEL];
__device__ float  g_pkv[S_LEN * 2 * KV_DIM];
__device__ __half g_q[S_LEN * DMODEL];           // roped+scaled q
__device__ __half g_k[S_LEN * KV_DIM];           // roped k
__device__ __half g_v[S_LEN * KV_DIM];           // v
__device__ __half g_o[S_LEN * DMODEL];           // attn out

// ----------------------------------------------------------------------------
// PTX helpers
// ----------------------------------------------------------------------------
__device__ __forceinline__ void mma16816(float* c, const uint32_t* a,
                                         uint32_t b0, uint32_t b1) {
    asm volatile(
        "mma.sync.aligned.m16n8k16.row.col.f32.f16.f16.f32 "
        "{%0,%1,%2,%3}, {%4,%5,%6,%7}, {%8,%9}, {%0,%1,%2,%3};"
        : "+f"(c[0]), "+f"(c[1]), "+f"(c[2]), "+f"(c[3])
        : "r"(a[0]), "r"(a[1]), "r"(a[2]), "r"(a[3]), "r"(b0), "r"(b1));
}
__device__ __forceinline__ void ldsm4(uint32_t* r, uint32_t addr) {
    asm volatile("ldmatrix.sync.aligned.m8n8.x4.shared.b16 {%0,%1,%2,%3}, [%4];"
                 : "=r"(r[0]), "=r"(r[1]), "=r"(r[2]), "=r"(r[3]) : "r"(addr));
}
__device__ __forceinline__ void ldsm4t(uint32_t* r, uint32_t addr) {
    asm volatile("ldmatrix.sync.aligned.m8n8.x4.trans.shared.b16 {%0,%1,%2,%3}, [%4];"
                 : "=r"(r[0]), "=r"(r[1]), "=r"(r[2]), "=r"(r[3]) : "r"(addr));
}
__device__ __forceinline__ void cp16(uint32_t saddr, const void* g) {
    asm volatile("cp.async.cg.shared.global [%0], [%1], 16;" :: "r"(saddr), "l"(g));
}
__device__ __forceinline__ void cp_commit() {
    asm volatile("cp.async.commit_group;" ::: "memory");
}
__device__ __forceinline__ uint32_t scvta(const void* p) {
    return (uint32_t)__cvta_generic_to_shared(p);
}
__device__ __forceinline__ uint32_t pack_h2(float a, float b) {
    __half2 t = __floats2half2_rn(a, b);
    return *(uint32_t*)&t;
}

// ----------------------------------------------------------------------------
// RMSNorm: one block per row; writes fp16
// ----------------------------------------------------------------------------
__global__ void rmsnorm_kernel(const float* __restrict__ x,
                               const float* __restrict__ g,
                               __half* __restrict__ h) {
    const int s = blockIdx.x;
    const float2* xr = (const float2*)(x + (size_t)s * DMODEL);
    const float2* gr = (const float2*)g;
    float sum = 0.f;
    for (int d = threadIdx.x; d < DMODEL / 2; d += 256) {
        float2 v = xr[d];
        sum += v.x * v.x + v.y * v.y;
    }
    __shared__ float red[8];
    #pragma unroll
    for (int o = 16; o > 0; o >>= 1) sum += __shfl_xor_sync(0xffffffffu, sum, o);
    if ((threadIdx.x & 31) == 0) red[threadIdx.x >> 5] = sum;
    __syncthreads();
    if (threadIdx.x < 32) {
        float v = (threadIdx.x < 8) ? red[threadIdx.x] : 0.f;
        #pragma unroll
        for (int o = 4; o > 0; o >>= 1) v += __shfl_xor_sync(0xffffffffu, v, o);
        if (threadIdx.x == 0) red[0] = v;
    }
    __syncthreads();
    const float rinv = rsqrtf(red[0] / (float)DMODEL + 1e-9f);
    uint32_t* ph = (uint32_t*)(h + (size_t)s * DMODEL);
    for (int d = threadIdx.x; d < DMODEL / 2; d += 256) {
        const float2 v = xr[d];
        const float2 gg = gr[d];
        ph[d] = pack_h2(v.x * rinv * gg.x, v.y * rinv * gg.y);
    }
}

// ----------------------------------------------------------------------------
// Transpose to fp16: W[K,N] fp32 -> Wt [N,K] fp16
// ----------------------------------------------------------------------------
__global__ void transpose_half_kernel(const float* __restrict__ w,
                                      __half* __restrict__ t_out,
                                      int K, int N) {
    __shared__ float t[32][33];
    const int n0 = blockIdx.x * 32, k0 = blockIdx.y * 32;
    const int tx = threadIdx.x, ty = threadIdx.y;  // (32, 8)
    #pragma unroll
    for (int i = 0; i < 32; i += 8)
        t[ty + i][tx] = w[(size_t)(k0 + ty + i) * N + n0 + tx];
    __syncthreads();
    const int lt = ty * 32 + tx;
    const int n  = lt >> 3;
    const int kp = lt & 7;
    #pragma unroll
    for (int q = 0; q < 2; q++) {
        const int k2 = (kp + q * 8) * 2;
        const size_t o = (size_t)(n0 + n) * K + k0 + k2;
        *(uint32_t*)(t_out + o) = pack_h2(t[k2][n], t[k2 + 1][n]);
    }
}

// ----------------------------------------------------------------------------
// fp16 GEMM: C[M,N] = A @ B^T (+Res), fp32 acc.
// Block 128x128, BK=32, 256 thr = 8 warps (2Mx4N), 4-stage cp.async, 2 CTA/SM.
// ----------------------------------------------------------------------------
#define KP 40
#define NSTAGE 4
#define T_STG (128 * KP * 2)                 // 10240 bytes / array / stage
#define GEMM_SMEM (NSTAGE * 2 * T_STG)       // 81920

__global__ __launch_bounds__(256, 2) void mma_gemm_kernel(
    const __half* __restrict__ A, const __half* __restrict__ B,
    const float* __restrict__ Res, float* __restrict__ C,
    int N, int K) {
    extern __shared__ __align__(16) char sm[];
    const uint32_t smb = scvta(sm);
    const uint32_t oA = 0;
    const uint32_t oB = NSTAGE * T_STG;

    const int tid  = threadIdx.x;
    const int lane = tid & 31, wid = tid >> 5;
    const int bm = blockIdx.y * 128, bn = blockIdx.x * 128;
    const int wmb = (wid & 1) * 64;
    const int wnb = (wid >> 1) * 32;
    const int lr = lane >> 2, lc = (lane & 3) * 2;

    float acc[4][4][4];
    #pragma unroll
    for (int mt = 0; mt < 4; mt++)
        #pragma unroll
        for (int nt = 0; nt < 4; nt++)
            #pragma unroll
            for (int i = 0; i < 4; i++) acc[mt][nt][i] = 0.f;

    auto load_stage = [&](int s, int kc) {
        #pragma unroll
        for (int p = 0; p < 2; p++) {
            const int idx = tid + p * 256;
            const int r = idx >> 2, c8 = (idx & 3) * 8;
            const uint32_t off = (uint32_t)(r * KP + c8) * 2;
            cp16(smb + oA + s * T_STG + off, A + (size_t)(bm + r) * K + kc + c8);
            cp16(smb + oB + s * T_STG + off, B + (size_t)(bn + r) * K + kc + c8);
        }
    };

    const int nch = K >> 5;
    load_stage(0, 0);  cp_commit();
    load_stage(1, 32); cp_commit();
    load_stage(2, 64); cp_commit();

    const int a_row = lane & 15;
    const int a_kof = (lane >> 4) << 3;
    const int b_row = (lane & 7) + ((lane >> 4) << 3);
    const int b_kof = ((lane >> 3) & 1) << 3;

    for (int c = 0; c < nch; c++) {
        const int remaining = nch - 1 - c;
        if (remaining >= 2)      asm volatile("cp.async.wait_group 2;" ::: "memory");
        else if (remaining == 1) asm volatile("cp.async.wait_group 1;" ::: "memory");
        else                     asm volatile("cp.async.wait_group 0;" ::: "memory");
        __syncthreads();
        if (c + NSTAGE - 1 < nch) {
            load_stage((c + 3) % NSTAGE, (c + 3) * 32);
            cp_commit();
        }
        const int cur = c % NSTAGE;
        const uint32_t sA = smb + oA + cur * T_STG;
        const uint32_t sB = smb + oB + cur * T_STG;

        #pragma unroll
        for (int kk = 0; kk < 32; kk += 16) {
            uint32_t fa[4][4];
            #pragma unroll
            for (int mt = 0; mt < 4; mt++) {
                const uint32_t off = (uint32_t)((wmb + mt * 16 + a_row) * KP + kk + a_kof) * 2;
                ldsm4(fa[mt], sA + off);
            }
            #pragma unroll
            for (int p2 = 0; p2 < 2; p2++) {
                const uint32_t off = (uint32_t)((wnb + p2 * 16 + b_row) * KP + kk + b_kof) * 2;
                uint32_t rb[4];
                ldsm4(rb, sB + off);
                #pragma unroll
                for (int mt = 0; mt < 4; mt++) {
                    mma16816(acc[mt][2 * p2],     fa[mt], rb[0], rb[1]);
                    mma16816(acc[mt][2 * p2 + 1], fa[mt], rb[2], rb[3]);
                }
            }
        }
        __syncthreads();
    }

    #pragma unroll
    for (int mt = 0; mt < 4; mt++) {
        const int row0 = bm + wmb + mt * 16 + lr;
        #pragma unroll
        for (int nt = 0; nt < 4; nt++) {
            const int col = bn + wnb + nt * 8 + lc;
            float2 v0 = make_float2(acc[mt][nt][0], acc[mt][nt][1]);
            float2 v1 = make_float2(acc[mt][nt][2], acc[mt][nt][3]);
            if (Res) {
                const float2 q0 = *(const float2*)(Res + (size_t)row0 * N + col);
                const float2 q1 = *(const float2*)(Res + (size_t)(row0 + 8) * N + col);
                v0.x += q0.x; v0.y += q0.y;
                v1.x += q1.x; v1.y += q1.y;
            }
            *(float2*)(C + (size_t)row0 * N + col) = v0;
            *(float2*)(C + (size_t)(row0 + 8) * N + col) = v1;
        }
    }
}

// ----------------------------------------------------------------------------
// RoPE + scale -> fp16
// ----------------------------------------------------------------------------
__global__ void rope_half_kernel(const float* __restrict__ src, int src_stride,
                                 __half* __restrict__ oh,
                                 int o_stride, int H, float scale, int total) {
    int idx = blockIdx.x * blockDim.x + threadIdx.x;
    if (idx >= total) return;
    const int i2 = idx & 15;
    const int h = (idx >> 4) % H;
    const int s = idx / (16 * H);
    const float* p = src + (size_t)s * src_stride + h * HD;
    float y[4];
    #pragma unroll
    for (int q = 0; q < 2; q++) {
        const int i = 2 * i2 + q;
        const double inv = pow(10000.0, -(double)(2 * i) / (double)HD);
        const double ang = (double)s * inv;
        const float cs = (float)cos(ang);
        const float sn = (float)sin(ang);
        const float x1 = p[i], x2 = p[i + 32];
        y[q]     = (x1 * cs - x2 * sn) * scale;
        y[2 + q] = (x1 * sn + x2 * cs) * scale;
    }
    __half* ph = oh + (size_t)s * o_stride + h * HD;
    *(uint32_t*)(ph + 2 * i2)      = pack_h2(y[0], y[1]);
    *(uint32_t*)(ph + 2 * i2 + 32) = pack_h2(y[2], y[3]);
}

// ----------------------------------------------------------------------------
// Strided fp16 convert for V
// ----------------------------------------------------------------------------
__global__ void split_v_kernel(const float* __restrict__ src,
                               __half* __restrict__ hi) {
    int i = blockIdx.x * blockDim.x + threadIdx.x;
    if (i >= S_LEN * KV_DIM / 2) return;
    const int s = i >> 8, c2 = (i & 255) * 2;
    const float2 v = *(const float2*)(src + (size_t)s * (2 * KV_DIM) + KV_DIM + c2);
    *(uint32_t*)(hi + (size_t)s * KV_DIM + c2) = pack_h2(v.x, v.y);
}

// ----------------------------------------------------------------------------
// Tensor-core causal GQA flash attention (fp16).
// Grid (S/128, HQ). 256 threads = 8 warps x 16 q-rows. KV tiles of 64,
// double-buffered with cp.async.
// ----------------------------------------------------------------------------
#define AQP 72
#define KV_STG 18432   // bytes per stage (K 9216 + V 9216)

__global__ __launch_bounds__(256) void attn_mma_kernel(
    const __half* __restrict__ qg, const __half* __restrict__ kg,
    const __half* __restrict__ vg, __half* __restrict__ og) {
    __shared__ __align__(16) char sbuf[2 * KV_STG];
    const uint32_t smb = scvta(sbuf);
    __half* QH = (__half*)sbuf;                 // [128][72] staging (reused)

    const int qt = blockIdx.x, h = blockIdx.y;
    const int kvh = h >> 2;
    const int tid = threadIdx.x, lane = tid & 31, wid = tid >> 5;
    const int lr = lane >> 2, lc = (lane & 3) * 2;

    // ---- stage Q (128 rows x 64 halves = 1024 chunks of 8 halves) ----
    #pragma unroll
    for (int p = 0; p < 4; p++) {
        const int idx = tid + p * 256;
        const int r = idx >> 3, c8 = (idx & 7) * 8;
        const size_t go = (size_t)(qt * 128 + r) * DMODEL + h * HD + c8;
        *(uint4*)(QH + r * AQP + c8) = *(const uint4*)(qg + go);
    }
    __syncthreads();

    uint32_t qf[4][4];
    {
        const int a_row = lane & 15;
        const int a_kof = (lane >> 4) << 3;
        #pragma unroll
        for (int ks = 0; ks < 4; ks++) {
            const uint32_t off = (uint32_t)((wid * 16 + a_row) * AQP + ks * 16 + a_kof) * 2;
            ldsm4(qf[ks], smb + off);
        }
    }
    __syncthreads();

    float o[8][4];
    #pragma unroll
    for (int n = 0; n < 8; n++)
        #pragma unroll
        for (int i = 0; i < 4; i++) o[n][i] = 0.f;
    float m0 = -1e30f, m1 = -1e30f, l0 = 0.f, l1 = 0.f;

    const int row0g = qt * 128 + wid * 16 + lr;
    const int row1g = row0g + 8;
    const int nkt = 2 * qt + 2;

    const int b_row = (lane & 7) + ((lane >> 4) << 3);
    const int b_kof = ((lane >> 3) & 1) << 3;
    const int v_row = lane & 15;
    const int v_col = (lane >> 4) << 3;

    auto load_kv = [&](int stage, int kt) {
        const uint32_t base = smb + stage * KV_STG;
        #pragma unroll
        for (int p = 0; p < 2; p++) {
            const int idx = tid + p * 256;
            const int r = idx >> 3, c8 = (idx & 7) * 8;
            const size_t go = (size_t)(kt * 64 + r) * KV_DIM + kvh * HD + c8;
            const uint32_t off = (uint32_t)(r * AQP + c8) * 2;
            cp16(base + off,        kg + go);
            cp16(base + 9216 + off, vg + go);
        }
    };

    load_kv(0, 0);
    cp_commit();

    for (int kt = 0; kt < nkt; kt++) {
        if (kt + 1 < nkt) {
            load_kv((kt + 1) & 1, kt + 1);
            cp_commit();
            asm volatile("cp.async.wait_group 1;" ::: "memory");
        } else {
            asm volatile("cp.async.wait_group 0;" ::: "memory");
        }
        __syncthreads();
        const uint32_t sK = smb + (kt & 1) * KV_STG;
        const uint32_t sV = sK + 9216;

        // ---- S = Q K^T ----
        float s[8][4];
        #pragma unroll
        for (int n = 0; n < 8; n++)
            #pragma unroll
            for (int i = 0; i < 4; i++) s[n][i] = 0.f;
        #pragma unroll
        for (int ks = 0; ks < 4; ks++) {
            #pragma unroll
            for (int p2 = 0; p2 < 4; p2++) {
                const uint32_t off = (uint32_t)((p2 * 16 + b_row) * AQP + ks * 16 + b_kof) * 2;
                uint32_t rk[4];
                ldsm4(rk, sK + off);
                mma16816(s[2 * p2],     qf[ks], rk[0], rk[1]);
                mma16816(s[2 * p2 + 1], qf[ks], rk[2], rk[3]);
            }
        }

        // ---- causal mask ----
        if (kt >= 2 * qt) {
            #pragma unroll
            for (int n = 0; n < 8; n++) {
                const int colb = kt * 64 + n * 8 + lc;
                if (colb     > row0g) s[n][0] = -1e30f;
                if (colb + 1 > row0g) s[n][1] = -1e30f;
                if (colb     > row1g) s[n][2] = -1e30f;
                if (colb + 1 > row1g) s[n][3] = -1e30f;
            }
        }

        // ---- online softmax ----
        float tm0 = -1e30f, tm1 = -1e30f;
        #pragma unroll
        for (int n = 0; n < 8; n++) {
            tm0 = fmaxf(tm0, fmaxf(s[n][0], s[n][1]));
            tm1 = fmaxf(tm1, fmaxf(s[n][2], s[n][3]));
        }
        tm0 = fmaxf(tm0, __shfl_xor_sync(0xffffffffu, tm0, 1));
        tm0 = fmaxf(tm0, __shfl_xor_sync(0xffffffffu, tm0, 2));
        tm1 = fmaxf(tm1, __shfl_xor_sync(0xffffffffu, tm1, 1));
        tm1 = fmaxf(tm1, __shfl_xor_sync(0xffffffffu, tm1, 2));
        const float mn0 = fmaxf(m0, tm0), mn1 = fmaxf(m1, tm1);
        const float a0 = __expf(m0 - mn0), a1 = __expf(m1 - mn1);
        m0 = mn0; m1 = mn1;

        uint32_t pA[8], pB[8];
        float rs0 = 0.f, rs1 = 0.f;
        #pragma unroll
        for (int n = 0; n < 8; n++) {
            const float p0 = __expf(s[n][0] - m0);
            const float p1 = __expf(s[n][1] - m0);
            const float p2 = __expf(s[n][2] - m1);
            const float p3 = __expf(s[n][3] - m1);
            rs0 += p0 + p1; rs1 += p2 + p3;
            pA[n] = pack_h2(p0, p1);
            pB[n] = pack_h2(p2, p3);
        }
        rs0 += __shfl_xor_sync(0xffffffffu, rs0, 1);
        rs0 += __shfl_xor_sync(0xffffffffu, rs0, 2);
        rs1 += __shfl_xor_sync(0xffffffffu, rs1, 1);
        rs1 += __shfl_xor_sync(0xffffffffu, rs1, 2);
        l0 = l0 * a0 + rs0;
        l1 = l1 * a1 + rs1;
        #pragma unroll
        for (int n = 0; n < 8; n++) {
            o[n][0] *= a0; o[n][1] *= a0;
            o[n][2] *= a1; o[n][3] *= a1;
        }

        // ---- O += P V ----
        #pragma unroll
        for (int j = 0; j < 4; j++) {
            uint32_t aP[4] = {pA[2*j], pB[2*j], pA[2*j+1], pB[2*j+1]};
            #pragma unroll
            for (int p2 = 0; p2 < 4; p2++) {
                const uint32_t off =
                    (uint32_t)((j * 16 + v_row) * AQP + p2 * 16 + v_col) * 2;
                uint32_t rv[4];
                ldsm4t(rv, sV + off);
                mma16816(o[2 * p2],     aP, rv[0], rv[1]);
                mma16816(o[2 * p2 + 1], aP, rv[2], rv[3]);
            }
        }
        __syncthreads();
    }

    // ---- epilogue ----
    const float i0 = 1.f / l0, i1 = 1.f / l1;
    #pragma unroll
    for (int n = 0; n < 8; n++) {
        const int col = h * HD + n * 8 + lc;
        *(uint32_t*)(og + (size_t)row0g * DMODEL + col) =
            pack_h2(o[n][0] * i0, o[n][1] * i0);
        *(uint32_t*)(og + (size_t)row1g * DMODEL + col) =
            pack_h2(o[n][2] * i1, o[n][3] * i1);
    }
}

// ----------------------------------------------------------------------------
// Launch
// ----------------------------------------------------------------------------
extern "C" void kernel_launch(void* const* d_in, const int* in_sizes, int n_in,
                              void* d_out, int out_size) {
    const float* x  = (const float*)d_in[0];
    const float* g  = (const float*)d_in[1];
    const float* wq = (const float*)d_in[2];
    const float* wk = (const float*)d_in[3];
    const float* wv = (const float*)d_in[4];
    const float* wo = (const float*)d_in[5];
    float* out = (float*)d_out;

    static bool inited = false;
    static __half *hh, *wqt, *kvt, *wot, *q16, *k16, *v16, *o16;
    static float *pq, *pkv;
    if (!inited) {
        inited = true;
        cudaFuncSetAttribute(mma_gemm_kernel,
                             cudaFuncAttributeMaxDynamicSharedMemorySize, GEMM_SMEM);
        cudaGetSymbolAddress((void**)&hh,  g_h);
        cudaGetSymbolAddress((void**)&wqt, g_wqt);
        cudaGetSymbolAddress((void**)&kvt, g_kvt);
        cudaGetSymbolAddress((void**)&wot, g_wot);
        cudaGetSymbolAddress((void**)&q16, g_q);
        cudaGetSymbolAddress((void**)&k16, g_k);
        cudaGetSymbolAddress((void**)&v16, g_v);
        cudaGetSymbolAddress((void**)&o16, g_o);
        cudaGetSymbolAddress((void**)&pq,  g_pq);
        cudaGetSymbolAddress((void**)&pkv, g_pkv);
    }

    // 1) RMSNorm -> fp16
    rmsnorm_kernel<<<S_LEN, 256>>>(x, g, hh);

    // 2) Weight transposes (fp16)
    dim3 tb(32, 8);
    transpose_half_kernel<<<dim3(DMODEL / 32, DMODEL / 32), tb>>>(wq, wqt, DMODEL, DMODEL);
    transpose_half_kernel<<<dim3(KV_DIM / 32, DMODEL / 32), tb>>>(wk, kvt, DMODEL, KV_DIM);
    transpose_half_kernel<<<dim3(KV_DIM / 32, DMODEL / 32), tb>>>(
        wv, kvt + (size_t)KV_DIM * DMODEL, DMODEL, KV_DIM);
    transpose_half_kernel<<<dim3(DMODEL / 32, DMODEL / 32), tb>>>(wo, wot, DMODEL, DMODEL);

    // 3) Projections
    mma_gemm_kernel<<<dim3(DMODEL / 128, S_LEN / 128), 256, GEMM_SMEM>>>(
        hh, wqt, nullptr, pq, DMODEL, DMODEL);
    mma_gemm_kernel<<<dim3(2 * KV_DIM / 128, S_LEN / 128), 256, GEMM_SMEM>>>(
        hh, kvt, nullptr, pkv, 2 * KV_DIM, DMODEL);

    // 4) RoPE + converts
    {
        const int tq = S_LEN * HQ * 16;
        rope_half_kernel<<<(tq + 255) / 256, 256>>>(pq, DMODEL, q16, DMODEL, HQ, 0.125f, tq);
        const int tk = S_LEN * HKV * 16;
        rope_half_kernel<<<(tk + 255) / 256, 256>>>(pkv, 2 * KV_DIM, k16, KV_DIM, HKV, 1.0f, tk);
        split_v_kernel<<<(S_LEN * KV_DIM / 2 + 255) / 256, 256>>>(pkv, v16);
    }

    // 5) Attention
    attn_mma_kernel<<<dim3(S_LEN / 128, HQ), 256>>>(q16, k16, v16, o16);

    // 6) Output projection + residual
    mma_gemm_kernel<<<dim3(DMODEL / 128, S_LEN / 128), 256, GEMM_SMEM>>>(
        o16, wot, x, out, DMODEL, DMODEL);
}

// round 15
// speedup vs baseline: 1.2441x; 1.0177x over previous
#include <cuda_runtime.h>
#include <cuda_fp16.h>
#include <cstdint>
#include <math.h>

// ----------------------------------------------------------------------------
// Problem constants
// ----------------------------------------------------------------------------
#define S_LEN   2048
#define DMODEL  2048
#define HQ      32
#define HKV     8
#define HD      64
#define KV_DIM  (HKV*HD)   // 512
#define QKV_N   (DMODEL + 2 * KV_DIM)   // 3072

// ----------------------------------------------------------------------------
// Scratch (static __device__ arrays: allocation-free)
// ----------------------------------------------------------------------------
__device__ __half g_h[S_LEN * DMODEL];            // rmsnorm out fp16
__device__ __half g_wqkvt[QKV_N * DMODEL];        // [wq^T; wk^T; wv^T] fp16 [N,K]
__device__ __half g_wot[DMODEL * DMODEL];
__device__ __half g_pqkv[S_LEN * QKV_N];          // fused projection out (fp16)
__device__ __half g_q[S_LEN * DMODEL];            // roped+scaled q
__device__ __half g_k[S_LEN * KV_DIM];            // roped k
__device__ __half g_o[S_LEN * DMODEL];            // attn out

// ----------------------------------------------------------------------------
// PTX helpers
// ----------------------------------------------------------------------------
__device__ __forceinline__ void mma16816(float* c, const uint32_t* a,
                                         uint32_t b0, uint32_t b1) {
    asm volatile(
        "mma.sync.aligned.m16n8k16.row.col.f32.f16.f16.f32 "
        "{%0,%1,%2,%3}, {%4,%5,%6,%7}, {%8,%9}, {%0,%1,%2,%3};"
        : "+f"(c[0]), "+f"(c[1]), "+f"(c[2]), "+f"(c[3])
        : "r"(a[0]), "r"(a[1]), "r"(a[2]), "r"(a[3]), "r"(b0), "r"(b1));
}
__device__ __forceinline__ void ldsm4(uint32_t* r, uint32_t addr) {
    asm volatile("ldmatrix.sync.aligned.m8n8.x4.shared.b16 {%0,%1,%2,%3}, [%4];"
                 : "=r"(r[0]), "=r"(r[1]), "=r"(r[2]), "=r"(r[3]) : "r"(addr));
}
__device__ __forceinline__ void ldsm4t(uint32_t* r, uint32_t addr) {
    asm volatile("ldmatrix.sync.aligned.m8n8.x4.trans.shared.b16 {%0,%1,%2,%3}, [%4];"
                 : "=r"(r[0]), "=r"(r[1]), "=r"(r[2]), "=r"(r[3]) : "r"(addr));
}
__device__ __forceinline__ void cp16(uint32_t saddr, const void* g) {
    asm volatile("cp.async.cg.shared.global [%0], [%1], 16;" :: "r"(saddr), "l"(g));
}
__device__ __forceinline__ void cp_commit() {
    asm volatile("cp.async.commit_group;" ::: "memory");
}
__device__ __forceinline__ uint32_t scvta(const void* p) {
    return (uint32_t)__cvta_generic_to_shared(p);
}
__device__ __forceinline__ uint32_t pack_h2(float a, float b) {
    __half2 t = __floats2half2_rn(a, b);
    return *(uint32_t*)&t;
}

// ----------------------------------------------------------------------------
// RMSNorm: one block per row; writes fp16
// ----------------------------------------------------------------------------
__global__ void rmsnorm_kernel(const float* __restrict__ x,
                               const float* __restrict__ g,
                               __half* __restrict__ h) {
    const int s = blockIdx.x;
    const float2* xr = (const float2*)(x + (size_t)s * DMODEL);
    const float2* gr = (const float2*)g;
    float sum = 0.f;
    for (int d = threadIdx.x; d < DMODEL / 2; d += 256) {
        float2 v = xr[d];
        sum += v.x * v.x + v.y * v.y;
    }
    __shared__ float red[8];
    #pragma unroll
    for (int o = 16; o > 0; o >>= 1) sum += __shfl_xor_sync(0xffffffffu, sum, o);
    if ((threadIdx.x & 31) == 0) red[threadIdx.x >> 5] = sum;
    __syncthreads();
    if (threadIdx.x < 32) {
        float v = (threadIdx.x < 8) ? red[threadIdx.x] : 0.f;
        #pragma unroll
        for (int o = 4; o > 0; o >>= 1) v += __shfl_xor_sync(0xffffffffu, v, o);
        if (threadIdx.x == 0) red[0] = v;
    }
    __syncthreads();
    const float rinv = rsqrtf(red[0] / (float)DMODEL + 1e-9f);
    uint32_t* ph = (uint32_t*)(h + (size_t)s * DMODEL);
    for (int d = threadIdx.x; d < DMODEL / 2; d += 256) {
        const float2 v = xr[d];
        const float2 gg = gr[d];
        ph[d] = pack_h2(v.x * rinv * gg.x, v.y * rinv * gg.y);
    }
}

// ----------------------------------------------------------------------------
// Transpose to fp16: W[K,N] fp32 -> Wt [N,K] fp16
// ----------------------------------------------------------------------------
__global__ void transpose_half_kernel(const float* __restrict__ w,
                                      __half* __restrict__ t_out,
                                      int K, int N) {
    __shared__ float t[32][33];
    const int n0 = blockIdx.x * 32, k0 = blockIdx.y * 32;
    const int tx = threadIdx.x, ty = threadIdx.y;  // (32, 8)
    #pragma unroll
    for (int i = 0; i < 32; i += 8)
        t[ty + i][tx] = w[(size_t)(k0 + ty + i) * N + n0 + tx];
    __syncthreads();
    const int lt = ty * 32 + tx;
    const int n  = lt >> 3;
    const int kp = lt & 7;
    #pragma unroll
    for (int q = 0; q < 2; q++) {
        const int k2 = (kp + q * 8) * 2;
        const size_t o = (size_t)(n0 + n) * K + k0 + k2;
        *(uint32_t*)(t_out + o) = pack_h2(t[k2][n], t[k2 + 1][n]);
    }
}

// ----------------------------------------------------------------------------
// fp16 GEMM: C[M,N] = A @ B^T (+Res if fp32 out), fp32 acc.
// Block 128x128, BK=32, 256 thr = 8 warps (2Mx4N), 4-stage cp.async,
// single barrier per mainloop iteration, 2 CTA/SM.
// FP16OUT: write __half (no residual). else: float with optional residual.
// ----------------------------------------------------------------------------
#define KP 40
#define NSTAGE 4
#define T_STG (128 * KP * 2)                 // 10240 bytes / array / stage
#define GEMM_SMEM (NSTAGE * 2 * T_STG)       // 81920

template<bool FP16OUT>
__global__ __launch_bounds__(256, 2) void mma_gemm_kernel(
    const __half* __restrict__ A, const __half* __restrict__ B,
    const float* __restrict__ Res, void* __restrict__ Cv,
    int N, int K) {
    extern __shared__ __align__(16) char sm[];
    const uint32_t smb = scvta(sm);
    const uint32_t oA = 0;
    const uint32_t oB = NSTAGE * T_STG;

    const int tid  = threadIdx.x;
    const int lane = tid & 31, wid = tid >> 5;
    const int bm = blockIdx.y * 128, bn = blockIdx.x * 128;
    const int wmb = (wid & 1) * 64;
    const int wnb = (wid >> 1) * 32;
    const int lr = lane >> 2, lc = (lane & 3) * 2;

    float acc[4][4][4];
    #pragma unroll
    for (int mt = 0; mt < 4; mt++)
        #pragma unroll
        for (int nt = 0; nt < 4; nt++)
            #pragma unroll
            for (int i = 0; i < 4; i++) acc[mt][nt][i] = 0.f;

    auto load_stage = [&](int s, int kc) {
        #pragma unroll
        for (int p = 0; p < 2; p++) {
            const int idx = tid + p * 256;
            const int r = idx >> 2, c8 = (idx & 3) * 8;
            const uint32_t off = (uint32_t)(r * KP + c8) * 2;
            cp16(smb + oA + s * T_STG + off, A + (size_t)(bm + r) * K + kc + c8);
            cp16(smb + oB + s * T_STG + off, B + (size_t)(bn + r) * K + kc + c8);
        }
    };

    const int nch = K >> 5;
    load_stage(0, 0);  cp_commit();
    load_stage(1, 32); cp_commit();
    load_stage(2, 64); cp_commit();

    const int a_row = lane & 15;
    const int a_kof = (lane >> 4) << 3;
    const int b_row = (lane & 7) + ((lane >> 4) << 3);
    const int b_kof = ((lane >> 3) & 1) << 3;

    for (int c = 0; c < nch; c++) {
        const int remaining = nch - 1 - c;
        if (remaining >= 2)      asm volatile("cp.async.wait_group 2;" ::: "memory");
        else if (remaining == 1) asm volatile("cp.async.wait_group 1;" ::: "memory");
        else                     asm volatile("cp.async.wait_group 0;" ::: "memory");
        __syncthreads();   // stage c visible; all warps done reading stage (c-1)
        if (c + NSTAGE - 1 < nch) {
            load_stage((c + 3) % NSTAGE, (c + 3) * 32);
            cp_commit();
        }
        const int cur = c % NSTAGE;
        const uint32_t sA = smb + oA + cur * T_STG;
        const uint32_t sB = smb + oB + cur * T_STG;

        #pragma unroll
        for (int kk = 0; kk < 32; kk += 16) {
            uint32_t fa[4][4];
            #pragma unroll
            for (int mt = 0; mt < 4; mt++) {
                const uint32_t off = (uint32_t)((wmb + mt * 16 + a_row) * KP + kk + a_kof) * 2;
                ldsm4(fa[mt], sA + off);
            }
            #pragma unroll
            for (int p2 = 0; p2 < 2; p2++) {
                const uint32_t off = (uint32_t)((wnb + p2 * 16 + b_row) * KP + kk + b_kof) * 2;
                uint32_t rb[4];
                ldsm4(rb, sB + off);
                #pragma unroll
                for (int mt = 0; mt < 4; mt++) {
                    mma16816(acc[mt][2 * p2],     fa[mt], rb[0], rb[1]);
                    mma16816(acc[mt][2 * p2 + 1], fa[mt], rb[2], rb[3]);
                }
            }
        }
    }

    #pragma unroll
    for (int mt = 0; mt < 4; mt++) {
        const int row0 = bm + wmb + mt * 16 + lr;
        #pragma unroll
        for (int nt = 0; nt < 4; nt++) {
            const int col = bn + wnb + nt * 8 + lc;
            if constexpr (FP16OUT) {
                __half* C = (__half*)Cv;
                *(uint32_t*)(C + (size_t)row0 * N + col) =
                    pack_h2(acc[mt][nt][0], acc[mt][nt][1]);
                *(uint32_t*)(C + (size_t)(row0 + 8) * N + col) =
                    pack_h2(acc[mt][nt][2], acc[mt][nt][3]);
            } else {
                float* C = (float*)Cv;
                float2 v0 = make_float2(acc[mt][nt][0], acc[mt][nt][1]);
                float2 v1 = make_float2(acc[mt][nt][2], acc[mt][nt][3]);
                if (Res) {
                    const float2 q0 = *(const float2*)(Res + (size_t)row0 * N + col);
                    const float2 q1 = *(const float2*)(Res + (size_t)(row0 + 8) * N + col);
                    v0.x += q0.x; v0.y += q0.y;
                    v1.x += q1.x; v1.y += q1.y;
                }
                *(float2*)(C + (size_t)row0 * N + col) = v0;
                *(float2*)(C + (size_t)(row0 + 8) * N + col) = v1;
            }
        }
    }
}

// ----------------------------------------------------------------------------
// RoPE + scale, fp16 in -> fp16 out
// ----------------------------------------------------------------------------
__global__ void rope_half_kernel(const __half* __restrict__ src, int src_stride,
                                 __half* __restrict__ oh,
                                 int o_stride, int H, float scale, int total) {
    int idx = blockIdx.x * blockDim.x + threadIdx.x;
    if (idx >= total) return;
    const int i2 = idx & 15;
    const int h = (idx >> 4) % H;
    const int s = idx / (16 * H);
    const __half* p = src + (size_t)s * src_stride + h * HD;
    float y[4];
    #pragma unroll
    for (int q = 0; q < 2; q++) {
        const int i = 2 * i2 + q;
        const double inv = pow(10000.0, -(double)(2 * i) / (double)HD);
        const double ang = (double)s * inv;
        const float cs = (float)cos(ang);
        const float sn = (float)sin(ang);
        const float x1 = __half2float(p[i]), x2 = __half2float(p[i + 32]);
        y[q]     = (x1 * cs - x2 * sn) * scale;
        y[2 + q] = (x1 * sn + x2 * cs) * scale;
    }
    __half* ph = oh + (size_t)s * o_stride + h * HD;
    *(uint32_t*)(ph + 2 * i2)      = pack_h2(y[0], y[1]);
    *(uint32_t*)(ph + 2 * i2 + 32) = pack_h2(y[2], y[3]);
}

// ----------------------------------------------------------------------------
// Tensor-core causal GQA flash attention (fp16).
// Grid (S/128, HQ). 256 threads = 8 warps x 16 q-rows, 2 CTAs/SM.
// KV tiles of 64, double-buffered cp.async. V read strided from pqkv.
// ----------------------------------------------------------------------------
#define AQP 72
#define KV_STG 18432   // bytes per stage (K 9216 + V 9216)

__global__ __launch_bounds__(256, 2) void attn_mma_kernel(
    const __half* __restrict__ qg, const __half* __restrict__ kg,
    const __half* __restrict__ vg, int vstride, __half* __restrict__ og) {
    __shared__ __align__(16) char sbuf[2 * KV_STG];
    const uint32_t smb = scvta(sbuf);
    __half* QH = (__half*)sbuf;                 // [128][72] staging (reused)

    const int qt = blockIdx.x, h = blockIdx.y;
    const int kvh = h >> 2;
    const int tid = threadIdx.x, lane = tid & 31, wid = tid >> 5;
    const int lr = lane >> 2, lc = (lane & 3) * 2;

    // ---- stage Q (128 rows x 64 halves = 1024 chunks of 8 halves) ----
    #pragma unroll
    for (int p = 0; p < 4; p++) {
        const int idx = tid + p * 256;
        const int r = idx >> 3, c8 = (idx & 7) * 8;
        const size_t go = (size_t)(qt * 128 + r) * DMODEL + h * HD + c8;
        *(uint4*)(QH + r * AQP + c8) = *(const uint4*)(qg + go);
    }
    __syncthreads();

    uint32_t qf[4][4];
    {
        const int a_row = lane & 15;
        const int a_kof = (lane >> 4) << 3;
        #pragma unroll
        for (int ks = 0; ks < 4; ks++) {
            const uint32_t off = (uint32_t)((wid * 16 + a_row) * AQP + ks * 16 + a_kof) * 2;
            ldsm4(qf[ks], smb + off);
        }
    }
    __syncthreads();

    float o[8][4];
    #pragma unroll
    for (int n = 0; n < 8; n++)
        #pragma unroll
        for (int i = 0; i < 4; i++) o[n][i] = 0.f;
    float m0 = -1e30f, m1 = -1e30f, l0 = 0.f, l1 = 0.f;

    const int row0g = qt * 128 + wid * 16 + lr;
    const int row1g = row0g + 8;
    const int nkt = 2 * qt + 2;

    const int b_row = (lane & 7) + ((lane >> 4) << 3);
    const int b_kof = ((lane >> 3) & 1) << 3;
    const int v_row = lane & 15;
    const int v_col = (lane >> 4) << 3;

    auto load_kv = [&](int stage, int kt) {
        const uint32_t base = smb + stage * KV_STG;
        #pragma unroll
        for (int p = 0; p < 2; p++) {
            const int idx = tid + p * 256;
            const int r = idx >> 3, c8 = (idx & 7) * 8;
            const uint32_t off = (uint32_t)(r * AQP + c8) * 2;
            cp16(base + off,
                 kg + (size_t)(kt * 64 + r) * KV_DIM + kvh * HD + c8);
            cp16(base + 9216 + off,
                 vg + (size_t)(kt * 64 + r) * vstride + kvh * HD + c8);
        }
    };

    load_kv(0, 0);
    cp_commit();

    for (int kt = 0; kt < nkt; kt++) {
        if (kt + 1 < nkt) {
            load_kv((kt + 1) & 1, kt + 1);
            cp_commit();
            asm volatile("cp.async.wait_group 1;" ::: "memory");
        } else {
            asm volatile("cp.async.wait_group 0;" ::: "memory");
        }
        __syncthreads();
        const uint32_t sK = smb + (kt & 1) * KV_STG;
        const uint32_t sV = sK + 9216;

        // ---- S = Q K^T ----
        float s[8][4];
        #pragma unroll
        for (int n = 0; n < 8; n++)
            #pragma unroll
            for (int i = 0; i < 4; i++) s[n][i] = 0.f;
        #pragma unroll
        for (int ks = 0; ks < 4; ks++) {
            #pragma unroll
            for (int p2 = 0; p2 < 4; p2++) {
                const uint32_t off = (uint32_t)((p2 * 16 + b_row) * AQP + ks * 16 + b_kof) * 2;
                uint32_t rk[4];
                ldsm4(rk, sK + off);
                mma16816(s[2 * p2],     qf[ks], rk[0], rk[1]);
                mma16816(s[2 * p2 + 1], qf[ks], rk[2], rk[3]);
            }
        }

        // ---- causal mask ----
        if (kt >= 2 * qt) {
            #pragma unroll
            for (int n = 0; n < 8; n++) {
                const int colb = kt * 64 + n * 8 + lc;
                if (colb     > row0g) s[n][0] = -1e30f;
                if (colb + 1 > row0g) s[n][1] = -1e30f;
                if (colb     > row1g) s[n][2] = -1e30f;
                if (colb + 1 > row1g) s[n][3] = -1e30f;
            }
        }

        // ---- online softmax ----
        float tm0 = -1e30f, tm1 = -1e30f;
        #pragma unroll
        for (int n = 0; n < 8; n++) {
            tm0 = fmaxf(tm0, fmaxf(s[n][0], s[n][1]));
            tm1 = fmaxf(tm1, fmaxf(s[n][2], s[n][3]));
        }
        tm0 = fmaxf(tm0, __shfl_xor_sync(0xffffffffu, tm0, 1));
        tm0 = fmaxf(tm0, __shfl_xor_sync(0xffffffffu, tm0, 2));
        tm1 = fmaxf(tm1, __shfl_xor_sync(0xffffffffu, tm1, 1));
        tm1 = fmaxf(tm1, __shfl_xor_sync(0xffffffffu, tm1, 2));
        const float mn0 = fmaxf(m0, tm0), mn1 = fmaxf(m1, tm1);
        const float a0 = __expf(m0 - mn0), a1 = __expf(m1 - mn1);
        m0 = mn0; m1 = mn1;

        uint32_t pA[8], pB[8];
        float rs0 = 0.f, rs1 = 0.f;
        #pragma unroll
        for (int n = 0; n < 8; n++) {
            const float p0 = __expf(s[n][0] - m0);
            const float p1 = __expf(s[n][1] - m0);
            const float p2 = __expf(s[n][2] - m1);
            const float p3 = __expf(s[n][3] - m1);
            rs0 += p0 + p1; rs1 += p2 + p3;
            pA[n] = pack_h2(p0, p1);
            pB[n] = pack_h2(p2, p3);
        }
        rs0 += __shfl_xor_sync(0xffffffffu, rs0, 1);
        rs0 += __shfl_xor_sync(0xffffffffu, rs0, 2);
        rs1 += __shfl_xor_sync(0xffffffffu, rs1, 1);
        rs1 += __shfl_xor_sync(0xffffffffu, rs1, 2);
        l0 = l0 * a0 + rs0;
        l1 = l1 * a1 + rs1;
        #pragma unroll
        for (int n = 0; n < 8; n++) {
            o[n][0] *= a0; o[n][1] *= a0;
            o[n][2] *= a1; o[n][3] *= a1;
        }

        // ---- O += P V ----
        #pragma unroll
        for (int j = 0; j < 4; j++) {
            uint32_t aP[4] = {pA[2*j], pB[2*j], pA[2*j+1], pB[2*j+1]};
            #pragma unroll
            for (int p2 = 0; p2 < 4; p2++) {
                const uint32_t off =
                    (uint32_t)((j * 16 + v_row) * AQP + p2 * 16 + v_col) * 2;
                uint32_t rv[4];
                ldsm4t(rv, sV + off);
                mma16816(o[2 * p2],     aP, rv[0], rv[1]);
                mma16816(o[2 * p2 + 1], aP, rv[2], rv[3]);
            }
        }
        __syncthreads();
    }

    // ---- epilogue ----
    const float i0 = 1.f / l0, i1 = 1.f / l1;
    #pragma unroll
    for (int n = 0; n < 8; n++) {
        const int col = h * HD + n * 8 + lc;
        *(uint32_t*)(og + (size_t)row0g * DMODEL + col) =
            pack_h2(o[n][0] * i0, o[n][1] * i0);
        *(uint32_t*)(og + (size_t)row1g * DMODEL + col) =
            pack_h2(o[n][2] * i1, o[n][3] * i1);
    }
}

// ----------------------------------------------------------------------------
// Launch
// ----------------------------------------------------------------------------
extern "C" void kernel_launch(void* const* d_in, const int* in_sizes, int n_in,
                              void* d_out, int out_size) {
    const float* x  = (const float*)d_in[0];
    const float* g  = (const float*)d_in[1];
    const float* wq = (const float*)d_in[2];
    const float* wk = (const float*)d_in[3];
    const float* wv = (const float*)d_in[4];
    const float* wo = (const float*)d_in[5];
    float* out = (float*)d_out;

    static bool inited = false;
    static __half *hh, *wqkvt, *wot, *pqkv, *q16, *k16, *o16;
    if (!inited) {
        inited = true;
        cudaFuncSetAttribute(mma_gemm_kernel<true>,
                             cudaFuncAttributeMaxDynamicSharedMemorySize, GEMM_SMEM);
        cudaFuncSetAttribute(mma_gemm_kernel<false>,
                             cudaFuncAttributeMaxDynamicSharedMemorySize, GEMM_SMEM);
        cudaGetSymbolAddress((void**)&hh,    g_h);
        cudaGetSymbolAddress((void**)&wqkvt, g_wqkvt);
        cudaGetSymbolAddress((void**)&wot,   g_wot);
        cudaGetSymbolAddress((void**)&pqkv,  g_pqkv);
        cudaGetSymbolAddress((void**)&q16,   g_q);
        cudaGetSymbolAddress((void**)&k16,   g_k);
        cudaGetSymbolAddress((void**)&o16,   g_o);
    }

    // 1) RMSNorm -> fp16
    rmsnorm_kernel<<<S_LEN, 256>>>(x, g, hh);

    // 2) Weight transposes (fp16): [wq^T; wk^T; wv^T] concatenated + wo^T
    dim3 tb(32, 8);
    transpose_half_kernel<<<dim3(DMODEL / 32, DMODEL / 32), tb>>>(wq, wqkvt, DMODEL, DMODEL);
    transpose_half_kernel<<<dim3(KV_DIM / 32, DMODEL / 32), tb>>>(
        wk, wqkvt + (size_t)DMODEL * DMODEL, DMODEL, KV_DIM);
    transpose_half_kernel<<<dim3(KV_DIM / 32, DMODEL / 32), tb>>>(
        wv, wqkvt + (size_t)(DMODEL + KV_DIM) * DMODEL, DMODEL, KV_DIM);
    transpose_half_kernel<<<dim3(DMODEL / 32, DMODEL / 32), tb>>>(wo, wot, DMODEL, DMODEL);

    // 3) Fused QKV projection (fp16 out)
    mma_gemm_kernel<true><<<dim3(QKV_N / 128, S_LEN / 128), 256, GEMM_SMEM>>>(
        hh, wqkvt, nullptr, pqkv, QKV_N, DMODEL);

    // 4) RoPE (q scaled by 1/sqrt(HD)); V used in place from pqkv
    {
        const int tq = S_LEN * HQ * 16;
        rope_half_kernel<<<(tq + 255) / 256, 256>>>(pqkv, QKV_N, q16, DMODEL, HQ, 0.125f, tq);
        const int tk = S_LEN * HKV * 16;
        rope_half_kernel<<<(tk + 255) / 256, 256>>>(pqkv + DMODEL, QKV_N, k16, KV_DIM, HKV, 1.0f, tk);
    }

    // 5) Attention (V strided directly out of pqkv)
    attn_mma_kernel<<<dim3(S_LEN / 128, HQ), 256>>>(
        q16, k16, pqkv + DMODEL + KV_DIM, QKV_N, o16);

    // 6) Output projection + residual (fp32 out)
    mma_gemm_kernel<false><<<dim3(DMODEL / 128, S_LEN / 128), 256, GEMM_SMEM>>>(
        o16, wot, x, out, DMODEL, DMODEL);
}